// round 8
// baseline (speedup 1.0000x reference)
#include <cuda_runtime.h>
#include <cuda_fp16.h>
#include <cstdint>

// ---------------- problem constants ----------------
#define TOKENS 256
#define IN_F   4096
#define OUT_F  14336
#define KC     128
#define NCHUNK (IN_F / KC)        // 32
#define M_TILE 128
#define NTHREADS 512
#define NBLOCKS (OUT_F / M_TILE)  // 112

// ---------------- scratch ----------------
__device__ __half g_xh[TOKENS * IN_F];

// ---------------- smem layout ----------------
// per stage: W = 2 sub-tiles (kh) of 128 rows x 128B = 2*16384
//            x = 2 sub-tiles of 256 rows x 128B = 2*32768
#define STAGE_BYTES 98304
#define SM_W(s)     ((s) * STAGE_BYTES)
#define SM_X(s)     (SM_W(s) + 32768)
#define SMEM_TOTAL  (2 * STAGE_BYTES)   // 196608 B

// ---------------- helpers ----------------
__device__ __forceinline__ uint32_t smem_u32(const void* p) {
    uint32_t a;
    asm("{ .reg .u64 t; cvta.to.shared.u64 t, %1; cvt.u32.u64 %0, t; }" : "=r"(a) : "l"(p));
    return a;
}

// 128B-row swizzle: XOR bits[6:4] with bits[9:7]
__device__ __forceinline__ uint32_t sw128(uint32_t off) {
    return off ^ ((off >> 3) & 0x70);
}

__device__ __forceinline__ void cp_async16(uint32_t dst, const void* src) {
    asm volatile("cp.async.cg.shared.global [%0], [%1], 16;" :: "r"(dst), "l"(src));
}
#define CP_COMMIT()  asm volatile("cp.async.commit_group;" ::: "memory")
#define CP_WAIT0()   asm volatile("cp.async.wait_group 0;" ::: "memory")

#define LDSM4(R, addr)                                                              \
    asm volatile("ldmatrix.sync.aligned.m8n8.x4.shared.b16 {%0,%1,%2,%3}, [%4];"    \
        : "=r"((R)[0]), "=r"((R)[1]), "=r"((R)[2]), "=r"((R)[3]) : "r"(addr))

#define MMA16816(C, A, B0, B1)                                                      \
    asm volatile("mma.sync.aligned.m16n8k16.row.col.f32.f16.f16.f32 "               \
        "{%0,%1,%2,%3}, {%4,%5,%6,%7}, {%8,%9}, {%0,%1,%2,%3};"                     \
        : "+f"((C)[0]), "+f"((C)[1]), "+f"((C)[2]), "+f"((C)[3])                    \
        : "r"((A)[0]), "r"((A)[1]), "r"((A)[2]), "r"((A)[3]), "r"(B0), "r"(B1))

// ---------------- prep: x -> fp16 ----------------
__global__ void prep_half_kernel(const float* __restrict__ x) {
    int i = blockIdx.x * blockDim.x + threadIdx.x;
    float2 v = ((const float2*)x)[i];
    __half2 h;
    h.x = __float2half_rn(v.x);
    h.y = __float2half_rn(v.y);
    ((__half2*)g_xh)[i] = h;
}

// ---------------- main GEMM kernel ----------------
__global__ void __launch_bounds__(NTHREADS, 1)
qlinear_kernel(const int* __restrict__ qw, const float* __restrict__ scale,
               const float* __restrict__ bias, float* __restrict__ out) {
    extern __shared__ char smem[];
    const uint32_t sb = smem_u32(smem);
    const int tid  = threadIdx.x;
    const int lane = tid & 31;
    const int wid  = tid >> 5;
    const int wm   = wid & 3;   // 4 warps along M (32 rows each)
    const int wn   = wid >> 2;  // 4 warps along N (64 tokens each)
    const int out0 = blockIdx.x * M_TILE;

    // ---- W loader: thread t -> row t/4, ints [32q, 32q+32) of each 128-int chunk,
    //      split into two 16-int groups (g=0,1) to cap live regs at 16 ----
    const int wrow = tid >> 2;      // 0..127
    const int wq   = tid & 3;
    const int4* wrowp = (const int4*)(qw + (size_t)(out0 + wrow) * IN_F);
    const int wkh = wq >> 1;        // which K-64 sub-tile this thread's ints land in
    // byte offsets within sub-tile for group g: (wq&1)*64 + g*32 + {0,16}
    uint32_t w_sts[2][2];
    #pragma unroll
    for (int g = 0; g < 2; g++) {
        w_sts[g][0] = (uint32_t)wkh * 16384 + sw128((uint32_t)wrow * 128 + (uint32_t)(wq & 1) * 64 + g * 32);
        w_sts[g][1] = (uint32_t)wkh * 16384 + sw128((uint32_t)wrow * 128 + (uint32_t)(wq & 1) * 64 + g * 32 + 16);
    }

    const char* xh_b = (const char*)g_xh;

    // ---- ldmatrix base indices ----
    const int aRow = wm * 32 + (lane & 15);
    const int aKs  = (lane & 16) ? 16 : 0;
    const int bRow = wn * 64 + (lane & 7) + ((lane & 16) ? 8 : 0);
    const int bKs  = (lane & 8) ? 16 : 0;

// ks in 0..7; sub-tile kh = ks>>2, 32B k-block = (ks&3)*32
#define AADDR(base, ks, fm) ((base) + ((uint32_t)(ks) >> 2) * 16384 + \
    sw128((uint32_t)(aRow + (fm) * 16) * 128 + (uint32_t)((ks) & 3) * 32 + aKs))
#define BADDR(base, ks, fn) ((base) + ((uint32_t)(ks) >> 2) * 32768 + \
    sw128((uint32_t)(bRow + (fn) * 16) * 128 + (uint32_t)((ks) & 3) * 32 + bKs))

    float acc[2][8][4];
    #pragma unroll
    for (int i = 0; i < 2; i++)
        #pragma unroll
        for (int j = 0; j < 8; j++)
            #pragma unroll
            for (int k = 0; k < 4; k++) acc[i][j][k] = 0.0f;

    int4 v0, v1, v2, v3;

#define W_LDG(ci, g) do {                                                   \
        const int4* p_ = wrowp + (size_t)(ci) * 32 + wq * 8 + (g) * 4;      \
        v0 = p_[0]; v1 = p_[1]; v2 = p_[2]; v3 = p_[3];                     \
    } while (0)

#define W_STS(base, g) do {                                                 \
        __half2 h_[8];                                                      \
        h_[0] = __halves2half2(__int2half_rn(v0.x), __int2half_rn(v0.y));   \
        h_[1] = __halves2half2(__int2half_rn(v0.z), __int2half_rn(v0.w));   \
        h_[2] = __halves2half2(__int2half_rn(v1.x), __int2half_rn(v1.y));   \
        h_[3] = __halves2half2(__int2half_rn(v1.z), __int2half_rn(v1.w));   \
        h_[4] = __halves2half2(__int2half_rn(v2.x), __int2half_rn(v2.y));   \
        h_[5] = __halves2half2(__int2half_rn(v2.z), __int2half_rn(v2.w));   \
        h_[6] = __halves2half2(__int2half_rn(v3.x), __int2half_rn(v3.y));   \
        h_[7] = __halves2half2(__int2half_rn(v3.z), __int2half_rn(v3.w));   \
        uint32_t* p_ = (uint32_t*)h_;                                       \
        asm volatile("st.shared.v4.b32 [%0], {%1,%2,%3,%4};"                \
            :: "r"((base) + w_sts[g][0]), "r"(p_[0]), "r"(p_[1]), "r"(p_[2]), "r"(p_[3]) : "memory"); \
        asm volatile("st.shared.v4.b32 [%0], {%1,%2,%3,%4};"                \
            :: "r"((base) + w_sts[g][1]), "r"(p_[4]), "r"(p_[5]), "r"(p_[6]), "r"(p_[7]) : "memory"); \
    } while (0)

// x chunk ci -> stage base (8 x 16B units per thread; 256 rows x 256B)
#define X_CPASYNC(ci, base) do {                                            \
        _Pragma("unroll")                                                   \
        for (int j_ = 0; j_ < 8; j_++) {                                    \
            int u_ = tid + j_ * NTHREADS;      /* 0..4095 */                \
            int row_ = u_ >> 4, c_ = u_ & 15;                               \
            uint32_t d_ = (uint32_t)(c_ >> 3) * 32768 +                     \
                          sw128((uint32_t)row_ * 128 + (uint32_t)(c_ & 7) * 16); \
            size_t so_ = (size_t)row_ * (IN_F * 2) + (size_t)(ci) * (KC * 2) + (size_t)c_ * 16; \
            cp_async16((base) + d_, xh_b + so_);                            \
        }                                                                   \
        CP_COMMIT();                                                        \
    } while (0)

    // ---- prologue: chunk 0 -> stage 0 ----
    X_CPASYNC(0, sb + SM_X(0));
    W_LDG(0, 0); W_STS(sb + SM_W(0), 0);
    W_LDG(0, 1); W_STS(sb + SM_W(0), 1);
    CP_WAIT0();
    __syncthreads();

    for (int i = 0; i < NCHUNK; i++) {
        const int s = i & 1;
        const uint32_t sw_base  = sb + SM_W(s);
        const uint32_t sx_base  = sb + SM_X(s);
        const uint32_t swn_base = sb + SM_W(s ^ 1);
        const uint32_t sxn_base = sb + SM_X(s ^ 1);

        uint32_t bf[2][4];
        uint32_t af0[4], af1[4];

        LDSM4(bf[0], BADDR(sx_base, 0, 0));

        #pragma unroll
        for (int ks = 0; ks < 8; ks++) {
            LDSM4(af0, AADDR(sw_base, ks, 0));
            LDSM4(af1, AADDR(sw_base, ks, 1));
            #pragma unroll
            for (int fn = 0; fn < 4; fn++) {
                const int st = ks * 4 + fn;
                if (st < 31) {
                    const int ns = st + 1;
                    LDSM4(bf[ns & 1], BADDR(sx_base, ns >> 2, ns & 3));
                }
                const uint32_t* bb = bf[st & 1];
                MMA16816(acc[0][2 * fn],     af0, bb[0], bb[1]);
                MMA16816(acc[0][2 * fn + 1], af0, bb[2], bb[3]);
                MMA16816(acc[1][2 * fn],     af1, bb[0], bb[1]);
                MMA16816(acc[1][2 * fn + 1], af1, bb[2], bb[3]);
            }

            // hoisted next-chunk memory work, spread across ksteps
            if (i + 1 < NCHUNK) {
                if (ks == 0) {
                    X_CPASYNC(i + 1, sxn_base);
                } else if (ks == 1) {
                    W_LDG(i + 1, 0);
                } else if (ks == 3) {
                    W_STS(swn_base, 0);
                    W_LDG(i + 1, 1);
                } else if (ks == 5) {
                    W_STS(swn_base, 1);
                }
            }
        }

        CP_WAIT0();
        __syncthreads();
    }

    // ---- epilogue: fuse scale + bias ----
    const int m_base = out0 + wm * 32 + (lane >> 2);
    #pragma unroll
    for (int fm = 0; fm < 2; fm++) {
        const int m0 = m_base + fm * 16;
        const float s0 = scale[m0],     bi0 = bias[m0];
        const float s1 = scale[m0 + 8], bi1 = bias[m0 + 8];
        #pragma unroll
        for (int nf = 0; nf < 8; nf++) {
            const int t0 = wn * 64 + nf * 8 + (lane & 3) * 2;
            float* o = out + (size_t)t0 * OUT_F;
            o[m0]             = fmaf(acc[fm][nf][0], s0, bi0);
            o[OUT_F + m0]     = fmaf(acc[fm][nf][1], s0, bi0);
            o[m0 + 8]         = fmaf(acc[fm][nf][2], s1, bi1);
            o[OUT_F + m0 + 8] = fmaf(acc[fm][nf][3], s1, bi1);
        }
    }
}

// ---------------- launch ----------------
extern "C" void kernel_launch(void* const* d_in, const int* in_sizes, int n_in,
                              void* d_out, int out_size) {
    const float* x     = (const float*)d_in[0];
    const int*   qw    = (const int*)d_in[1];
    const float* scale = (const float*)d_in[2];
    const float* bias  = (const float*)d_in[3];
    float* out = (float*)d_out;

    prep_half_kernel<<<(TOKENS * IN_F / 2) / 256, 256>>>(x);

    cudaFuncSetAttribute(qlinear_kernel, cudaFuncAttributeMaxDynamicSharedMemorySize, SMEM_TOTAL);
    qlinear_kernel<<<NBLOCKS, NTHREADS, SMEM_TOTAL>>>(qw, scale, bias, out);
}

// round 9
// speedup vs baseline: 1.4915x; 1.4915x over previous
#include <cuda_runtime.h>
#include <cuda_fp16.h>
#include <cstdint>

// ---------------- problem constants ----------------
#define TOKENS 256
#define IN_F   4096
#define OUT_F  14336
#define KC     64
#define NCHUNK (IN_F / KC)        // 64
#define M_TILE 128
#define NTHREADS 512
#define NBLOCKS (OUT_F / M_TILE)  // 112

// ---------------- scratch ----------------
__device__ __half g_xh[TOKENS * IN_F];

// ---------------- smem layout ----------------
// per stage (128B rows): W 128x128B = 16384 | x 256x128B = 32768
#define STAGE_BYTES 49152
#define SM_W(s)     ((s) * STAGE_BYTES)
#define SM_X(s)     (SM_W(s) + 16384)
#define SMEM_TOTAL  (2 * STAGE_BYTES)   // 98304 B

// ---------------- helpers ----------------
__device__ __forceinline__ uint32_t smem_u32(const void* p) {
    uint32_t a;
    asm("{ .reg .u64 t; cvta.to.shared.u64 t, %1; cvt.u32.u64 %0, t; }" : "=r"(a) : "l"(p));
    return a;
}

// 128B-row swizzle: XOR bits[6:4] with bits[9:7]
__device__ __forceinline__ uint32_t sw128(uint32_t off) {
    return off ^ ((off >> 3) & 0x70);
}

__device__ __forceinline__ void cp_async16(uint32_t dst, const void* src) {
    asm volatile("cp.async.cg.shared.global [%0], [%1], 16;" :: "r"(dst), "l"(src));
}
#define CP_COMMIT()  asm volatile("cp.async.commit_group;" ::: "memory")
#define CP_WAIT0()   asm volatile("cp.async.wait_group 0;" ::: "memory")

#define LDSM4(R, addr)                                                              \
    asm volatile("ldmatrix.sync.aligned.m8n8.x4.shared.b16 {%0,%1,%2,%3}, [%4];"    \
        : "=r"((R)[0]), "=r"((R)[1]), "=r"((R)[2]), "=r"((R)[3]) : "r"(addr))

#define MMA16816(C, A, B0, B1)                                                      \
    asm volatile("mma.sync.aligned.m16n8k16.row.col.f32.f16.f16.f32 "               \
        "{%0,%1,%2,%3}, {%4,%5,%6,%7}, {%8,%9}, {%0,%1,%2,%3};"                     \
        : "+f"((C)[0]), "+f"((C)[1]), "+f"((C)[2]), "+f"((C)[3])                    \
        : "r"((A)[0]), "r"((A)[1]), "r"((A)[2]), "r"((A)[3]), "r"(B0), "r"(B1))

// ---------------- prep: x -> fp16 ----------------
__global__ void prep_half_kernel(const float* __restrict__ x) {
    int i = blockIdx.x * blockDim.x + threadIdx.x;
    float2 v = ((const float2*)x)[i];
    __half2 h;
    h.x = __float2half_rn(v.x);
    h.y = __float2half_rn(v.y);
    ((__half2*)g_xh)[i] = h;
}

// ---------------- main GEMM kernel ----------------
__global__ void __launch_bounds__(NTHREADS, 1)
qlinear_kernel(const int* __restrict__ qw, const float* __restrict__ scale,
               const float* __restrict__ bias, float* __restrict__ out) {
    extern __shared__ char smem[];
    const uint32_t sb = smem_u32(smem);
    const int tid  = threadIdx.x;
    const int lane = tid & 31;
    const int wid  = tid >> 5;
    const int wm   = wid & 3;   // 4 warps along M (32 rows each)
    const int wn   = wid >> 2;  // 4 warps along N (64 tokens each)
    const int out0 = blockIdx.x * M_TILE;

    // ---- W loader: thread t -> row t/4, two groups of 8 ints (8 regs live max) ----
    const int wrow = tid >> 2;      // 0..127
    const int wq   = tid & 3;
    const int4* wrowp = (const int4*)(qw + (size_t)(out0 + wrow) * IN_F);
    uint32_t w_sts[2];
    w_sts[0] = sw128((uint32_t)wrow * 128 + (uint32_t)wq * 32);
    w_sts[1] = sw128((uint32_t)wrow * 128 + (uint32_t)wq * 32 + 16);

    const char* xh_b = (const char*)g_xh;

    // ---- ldmatrix base indices ----
    const int aRow = wm * 32 + (lane & 15);
    const int aKs  = (lane & 16) ? 16 : 0;
    const int bRow = wn * 64 + (lane & 7) + ((lane & 16) ? 8 : 0);
    const int bKs  = (lane & 8) ? 16 : 0;

#define AADDR(base, ks, fm) ((base) + sw128((uint32_t)(aRow + (fm) * 16) * 128 + (uint32_t)(ks) * 32 + aKs))
#define BADDR(base, ks, fn) ((base) + sw128((uint32_t)(bRow + (fn) * 16) * 128 + (uint32_t)(ks) * 32 + bKs))

    float acc[2][8][4];
    #pragma unroll
    for (int i = 0; i < 2; i++)
        #pragma unroll
        for (int j = 0; j < 8; j++)
            #pragma unroll
            for (int k = 0; k < 4; k++) acc[i][j][k] = 0.0f;

    int4 v0, v1;   // 8-int W staging

#define W_LDG(ci, g) do {                                                   \
        const int4* p_ = wrowp + (size_t)(ci) * 16 + wq * 4 + (g) * 2;      \
        v0 = p_[0]; v1 = p_[1];                                             \
    } while (0)

#define W_STS(base, g) do {                                                 \
        __half2 h_[4];                                                      \
        h_[0] = __halves2half2(__int2half_rn(v0.x), __int2half_rn(v0.y));   \
        h_[1] = __halves2half2(__int2half_rn(v0.z), __int2half_rn(v0.w));   \
        h_[2] = __halves2half2(__int2half_rn(v1.x), __int2half_rn(v1.y));   \
        h_[3] = __halves2half2(__int2half_rn(v1.z), __int2half_rn(v1.w));   \
        uint32_t* p_ = (uint32_t*)h_;                                       \
        asm volatile("st.shared.v4.b32 [%0], {%1,%2,%3,%4};"                \
            :: "r"((base) + w_sts[g]), "r"(p_[0]), "r"(p_[1]), "r"(p_[2]), "r"(p_[3]) : "memory"); \
    } while (0)

#define X_CPASYNC(ci, base) do {                                            \
        _Pragma("unroll")                                                   \
        for (int j_ = 0; j_ < 4; j_++) {                                    \
            int u_ = tid + j_ * NTHREADS;      /* 0..2047 */                \
            int row_ = u_ >> 3, c_ = u_ & 7;                                \
            uint32_t d_ = sw128((uint32_t)row_ * 128 + (uint32_t)c_ * 16);  \
            size_t so_ = (size_t)row_ * (IN_F * 2) + (size_t)(ci) * (KC * 2) + (size_t)c_ * 16; \
            cp_async16((base) + d_, xh_b + so_);                            \
        }                                                                   \
        CP_COMMIT();                                                        \
    } while (0)

    // ---- prologue: chunk 0 -> stage 0 ----
    X_CPASYNC(0, sb + SM_X(0));
    W_LDG(0, 0); W_STS(sb + SM_W(0), 0);
    W_LDG(0, 1); W_STS(sb + SM_W(0), 1);
    CP_WAIT0();
    __syncthreads();

    for (int i = 0; i < NCHUNK; i++) {
        const int s = i & 1;
        const uint32_t sw_base  = sb + SM_W(s);
        const uint32_t sx_base  = sb + SM_X(s);
        const uint32_t swn_base = sb + SM_W(s ^ 1);
        const uint32_t sxn_base = sb + SM_X(s ^ 1);

        uint32_t bf[2][4];
        uint32_t af[2][2][4];   // double-buffered A frags

        // preload A(kstep 0) and B(step 0)
        LDSM4(af[0][0], AADDR(sw_base, 0, 0));
        LDSM4(af[0][1], AADDR(sw_base, 0, 1));
        LDSM4(bf[0], BADDR(sx_base, 0, 0));

        #pragma unroll
        for (int ks = 0; ks < 4; ks++) {
            const int cur = ks & 1;
            const int nxt = cur ^ 1;
            // prefetch next kstep's A frags into the other buffer
            if (ks < 3) {
                LDSM4(af[nxt][0], AADDR(sw_base, ks + 1, 0));
                LDSM4(af[nxt][1], AADDR(sw_base, ks + 1, 1));
            }
            #pragma unroll
            for (int fn = 0; fn < 4; fn++) {
                const int st = ks * 4 + fn;
                if (st < 15) {
                    const int ns = st + 1;
                    LDSM4(bf[ns & 1], BADDR(sx_base, ns >> 2, ns & 3));
                }
                const uint32_t* bb = bf[st & 1];
                MMA16816(acc[0][2 * fn],     af[cur][0], bb[0], bb[1]);
                MMA16816(acc[0][2 * fn + 1], af[cur][0], bb[2], bb[3]);
                MMA16816(acc[1][2 * fn],     af[cur][1], bb[0], bb[1]);
                MMA16816(acc[1][2 * fn + 1], af[cur][1], bb[2], bb[3]);
            }

            // hoisted next-chunk memory work, spread across ksteps
            if (i + 1 < NCHUNK) {
                if (ks == 0) {
                    X_CPASYNC(i + 1, sxn_base);
                } else if (ks == 1) {
                    W_LDG(i + 1, 0);
                } else if (ks == 2) {
                    W_STS(swn_base, 0);
                    W_LDG(i + 1, 1);
                } else {
                    W_STS(swn_base, 1);
                }
            }
        }

        CP_WAIT0();
        __syncthreads();
    }

    // ---- epilogue: fuse scale + bias ----
    const int m_base = out0 + wm * 32 + (lane >> 2);
    #pragma unroll
    for (int fm = 0; fm < 2; fm++) {
        const int m0 = m_base + fm * 16;
        const float s0 = scale[m0],     bi0 = bias[m0];
        const float s1 = scale[m0 + 8], bi1 = bias[m0 + 8];
        #pragma unroll
        for (int nf = 0; nf < 8; nf++) {
            const int t0 = wn * 64 + nf * 8 + (lane & 3) * 2;
            float* o = out + (size_t)t0 * OUT_F;
            o[m0]             = fmaf(acc[fm][nf][0], s0, bi0);
            o[OUT_F + m0]     = fmaf(acc[fm][nf][1], s0, bi0);
            o[m0 + 8]         = fmaf(acc[fm][nf][2], s1, bi1);
            o[OUT_F + m0 + 8] = fmaf(acc[fm][nf][3], s1, bi1);
        }
    }
}

// ---------------- launch ----------------
extern "C" void kernel_launch(void* const* d_in, const int* in_sizes, int n_in,
                              void* d_out, int out_size) {
    const float* x     = (const float*)d_in[0];
    const int*   qw    = (const int*)d_in[1];
    const float* scale = (const float*)d_in[2];
    const float* bias  = (const float*)d_in[3];
    float* out = (float*)d_out;

    prep_half_kernel<<<(TOKENS * IN_F / 2) / 256, 256>>>(x);

    cudaFuncSetAttribute(qlinear_kernel, cudaFuncAttributeMaxDynamicSharedMemorySize, SMEM_TOTAL);
    qlinear_kernel<<<NBLOCKS, NTHREADS, SMEM_TOTAL>>>(qw, scale, bias, out);
}